// round 16
// baseline (speedup 1.0000x reference)
#include <cuda_runtime.h>
#include <cuda_fp16.h>
#include <cstdint>

// Problem constants
#define Bb 2
#define Ss 2048
#define Dd 512
#define Hh 8
#define DHd 64
#define BSr (Bb*Ss)     // 4096 rows

// ---------------------------------------------------------------------------
// Global scratch (all u32 = f16x2 word = 2 fp16 elements).
// ---------------------------------------------------------------------------
__device__ __align__(16) uint32_t g_Xh16[4096*256];
__device__ __align__(16) uint32_t g_Xl16[4096*256];
__device__ __align__(16) uint32_t g_W16 [1536*256];
__device__ __align__(16) uint32_t g_Wo16[512*256];
__device__ __align__(16) uint32_t g_Oh16[4096*256];
__device__ __align__(16) uint32_t g_Ol16[4096*256];
__device__ __align__(16) uint32_t g_Q16 [Hh*Bb*Ss*32];
__device__ __align__(16) uint32_t g_K16 [Hh*Bb*Ss*32];
__device__ __align__(16) uint32_t g_V16 [Hh*Bb*Ss*32];
__device__ __align__(16) uint32_t g_SM16[(size_t)Bb*Ss*1024];

// ---------------------------------------------------------------------------
// helpers
// ---------------------------------------------------------------------------
__device__ __forceinline__ void mma_f16(float* d, const uint32_t* a,
                                        uint32_t b0, uint32_t b1) {
    asm volatile("mma.sync.aligned.m16n8k16.row.col.f32.f16.f16.f32 "
                 "{%0,%1,%2,%3}, {%4,%5,%6,%7}, {%8,%9}, {%0,%1,%2,%3};"
                 : "+f"(d[0]), "+f"(d[1]), "+f"(d[2]), "+f"(d[3])
                 : "r"(a[0]), "r"(a[1]), "r"(a[2]), "r"(a[3]), "r"(b0), "r"(b1));
}
__device__ __forceinline__ void ldsm4(uint32_t* r, uint32_t a) {
    asm volatile("ldmatrix.sync.aligned.m8n8.x4.shared.b16 {%0,%1,%2,%3}, [%4];"
                 : "=r"(r[0]), "=r"(r[1]), "=r"(r[2]), "=r"(r[3]) : "r"(a));
}
__device__ __forceinline__ void ldsm4t(uint32_t* r, uint32_t a) {
    asm volatile("ldmatrix.sync.aligned.m8n8.x4.trans.shared.b16 {%0,%1,%2,%3}, [%4];"
                 : "=r"(r[0]), "=r"(r[1]), "=r"(r[2]), "=r"(r[3]) : "r"(a));
}
__device__ __forceinline__ uint32_t smem_u32(const void* p) {
    uint32_t a;
    asm("{ .reg .u64 t; cvta.to.shared.u64 t, %1; cvt.u32.u64 %0, t; }"
        : "=r"(a) : "l"(p));
    return a;
}
__device__ __forceinline__ uint32_t pkh2(float x, float y) {
    __half2 h = __floats2half2_rn(x, y);
    return *(uint32_t*)&h;
}
__device__ __forceinline__ void splith2(float2 f, uint32_t& whi, uint32_t& wlo) {
    __half2 h = __floats2half2_rn(f.x, f.y);
    whi = *(uint32_t*)&h;
    float2 bk = __half22float2(h);
    __half2 l = __floats2half2_rn(f.x - bk.x, f.y - bk.y);
    wlo = *(uint32_t*)&l;
}
__device__ __forceinline__ float2 uph2(uint32_t w) {
    return __half22float2(*(__half2*)&w);
}
__device__ __forceinline__ void cpa16(uint32_t dst, const uint32_t* src) {
    asm volatile("cp.async.cg.shared.global [%0], [%1], 16;"
                 :: "r"(dst), "l"(src) : "memory");
}
#define CP_COMMIT() asm volatile("cp.async.commit_group;" ::: "memory")
#define CP_WAIT0()  asm volatile("cp.async.wait_group 0;" ::: "memory")
#define CP_WAIT1()  asm volatile("cp.async.wait_group 1;" ::: "memory")

// ---------------------------------------------------------------------------
// Kernel 0: precompute fp16 tables.
//   X -> Xhi/Xlo (split, ~exact), W/Wo -> single fp16,
//   shm = mask ? shift : 65504  (masked logits -> exp2 underflow -> exact 0)
// ---------------------------------------------------------------------------
#define PRE_TOTAL (1048576 + 393216 + 131072 + 4194304)

__global__ void presplit(const float* __restrict__ X,
                         const float* __restrict__ W,
                         const float* __restrict__ Wo,
                         const float* __restrict__ shift,
                         const float* __restrict__ mask) {
    for (int idx = blockIdx.x * blockDim.x + threadIdx.x;
         idx < PRE_TOTAL; idx += gridDim.x * blockDim.x) {
        if (idx < 1048576) {                    // X split
            int row = idx >> 8, wc = idx & 255;
            float2 f = *(const float2*)&X[(size_t)row * 512 + wc * 2];
            uint32_t hi, lo; splith2(f, hi, lo);
            g_Xh16[(size_t)row * 256 + wc] = hi;
            g_Xl16[(size_t)row * 256 + wc] = lo;
        } else if (idx < 1441792) {             // W single
            int p = idx - 1048576;
            int row = p >> 8, wc = p & 255;
            float2 f = *(const float2*)&W[(size_t)row * 512 + wc * 2];
            g_W16[(size_t)row * 256 + wc] = pkh2(f.x, f.y);
        } else if (idx < 1572864) {             // Wo single
            int p = idx - 1441792;
            int row = p >> 8, wc = p & 255;
            float2 f = *(const float2*)&Wo[(size_t)row * 512 + wc * 2];
            g_Wo16[(size_t)row * 256 + wc] = pkh2(f.x, f.y);
        } else {                                // fused shift/mask
            int p = idx - 1572864;
            int row = p >> 10, wc = p & 1023;
            float2 sh = *(const float2*)&shift[(size_t)row * 2048 + wc * 2];
            float2 mk = *(const float2*)&mask[(size_t)row * 2048 + wc * 2];
            float v0 = (mk.x != 0.f) ? sh.x : 65504.f;
            float v1 = (mk.y != 0.f) ? sh.y : 65504.f;
            g_SM16[(size_t)row * 1024 + wc] = pkh2(v0, v1);
        }
    }
}

// ---------------------------------------------------------------------------
// Unified fp16 2-pass GEMM, M-tile 64: C = (Ahi+Alo) @ B^T + bias, K=512.
// CTA tile 64x128, 8 warps 2(M)x4(N), warp tile 32x32.
// K chunks of 32 elems, 2-stage cp.async. A split fp16 (exact), B single fp16.
// MODE 0: A=Xhi/Xlo, B=W16 -> scatter single fp16 Q/K/V. grid (12, 64).
// MODE 1: A=Ohi/Olo, B=Wo16 -> fp32 out. grid (4, 64).
// ---------------------------------------------------------------------------
#define GSTR2 80
#define GSTAGE 20480          // Ahi 5120 | Alo 5120 | B 10240
#define GEMM_SMEM 40960

template<int MODE>
__global__ __launch_bounds__(256, 2) void tc_gemm(const float* __restrict__ bias,
                                                  float* __restrict__ out) {
    extern __shared__ char smg[];
    const uint32_t sb = smem_u32(smg);
    const int tid = threadIdx.x;
    const int lane = tid & 31;
    const int w = tid >> 5;
    const int g = lane >> 2;
    const int tg = lane & 3;
    const int r8 = lane & 7;
    const int mlo = (lane >> 3) & 1;
    const int mhi = lane >> 4;
    const int bm = blockIdx.y * 64;
    const int bn = blockIdx.x * 128;

    const uint32_t* Ah = (MODE == 0) ? g_Xh16 : g_Oh16;
    const uint32_t* Al = (MODE == 0) ? g_Xl16 : g_Ol16;
    const uint32_t* Bw = (MODE == 0) ? g_W16 : g_Wo16;

    const int wm = (w >> 2) * 32;      // 2 warps in M, 32 rows each
    const int wn = (w & 3) * 32;

    float acc[2][4][4];
#pragma unroll
    for (int mb = 0; mb < 2; mb++)
#pragma unroll
        for (int nb = 0; nb < 4; nb++)
#pragma unroll
            for (int q = 0; q < 4; q++) acc[mb][nb][q] = 0.f;

    const uint32_t aA = sb + (uint32_t)((wm + mlo * 8 + r8) * GSTR2 + mhi * 16);
    const uint32_t aB = sb + 10240 + (uint32_t)((wn + mhi * 8 + r8) * GSTR2 + mlo * 16);

    // stage chunk c into stage s: Ahi 256 + Alo 256 + B 512 uint4 = 4/thread
    auto stage_chunk = [&](int c, int s) {
        const int c0w = c * 16;
#pragma unroll
        for (int it = 0; it < 4; it++) {
            int item = tid + it * 256;
            if (item < 512) {
                int half = item >> 8;
                int idx = item & 255;
                int row = idx >> 2, c4 = idx & 3;
                const uint32_t* src = (half ? Al : Ah)
                                      + (size_t)(bm + row) * 256 + c0w + c4 * 4;
                cpa16(sb + s * GSTAGE + half * 5120
                         + (uint32_t)(row * GSTR2 + c4 * 16), src);
            } else {
                int idx = item - 512;
                int row = idx >> 2, c4 = idx & 3;
                const uint32_t* src = Bw + (size_t)(bn + row) * 256 + c0w + c4 * 4;
                cpa16(sb + s * GSTAGE + 10240
                         + (uint32_t)(row * GSTR2 + c4 * 16), src);
            }
        }
    };

    stage_chunk(0, 0);
    CP_COMMIT();

#pragma unroll 1
    for (int c = 0; c < 16; c++) {
        const int s = c & 1;
        if (c + 1 < 16) {
            stage_chunk(c + 1, s ^ 1);
            CP_COMMIT();
            CP_WAIT1();
        } else {
            CP_WAIT0();
        }
        __syncthreads();

        const uint32_t so = s * GSTAGE;
#pragma unroll
        for (int kk = 0; kk < 2; kk++) {
            uint32_t ah[2][4], al[2][4];
#pragma unroll
            for (int mb = 0; mb < 2; mb++) {
                ldsm4(ah[mb], aA + so + mb * (16 * GSTR2) + kk * 32);
                ldsm4(al[mb], aA + so + 5120 + mb * (16 * GSTR2) + kk * 32);
            }
#pragma unroll
            for (int j = 0; j < 2; j++) {
                uint32_t bf[4];
                ldsm4(bf, aB + so + j * (16 * GSTR2) + kk * 32);
#pragma unroll
                for (int mb = 0; mb < 2; mb++) {
                    mma_f16(acc[mb][2*j],   ah[mb], bf[0], bf[1]);
                    mma_f16(acc[mb][2*j+1], ah[mb], bf[2], bf[3]);
                    mma_f16(acc[mb][2*j],   al[mb], bf[0], bf[1]);
                    mma_f16(acc[mb][2*j+1], al[mb], bf[2], bf[3]);
                }
            }
        }
        __syncthreads();
    }

    // ---- epilogue ----
#pragma unroll
    for (int nb = 0; nb < 4; nb++) {
        if (MODE == 0) {
            const int nbb = bn + wn + nb * 8;
            const int h = nbb / 192;
            const int r = nbb - h * 192;
            const int t = r >> 6;
            uint32_t* dst = (t == 0) ? g_Q16 : (t == 1) ? g_K16 : g_V16;
            const int wc = ((r & 63) >> 1) + tg;
            const float2 bia = *(const float2*)&bias[nbb + 2 * tg];
#pragma unroll
            for (int mb = 0; mb < 2; mb++) {
#pragma unroll
                for (int hf = 0; hf < 2; hf++) {
                    const int m = bm + wm + mb * 16 + g + hf * 8;
                    const int bi = m >> 11, ss = m & 2047;
                    dst[((size_t)(h * Bb + bi) * Ss + ss) * 32 + wc] =
                        pkh2(acc[mb][nb][2*hf] + bia.x,
                             acc[mb][nb][2*hf + 1] + bia.y);
                }
            }
        } else {
            const int n0 = bn + wn + nb * 8 + 2 * tg;
            const float2 bia = *(const float2*)&bias[n0];
#pragma unroll
            for (int mb = 0; mb < 2; mb++) {
                const int m0 = bm + wm + mb * 16 + g;
                float2 v0; v0.x = acc[mb][nb][0] + bia.x; v0.y = acc[mb][nb][1] + bia.y;
                float2 v1; v1.x = acc[mb][nb][2] + bia.x; v1.y = acc[mb][nb][3] + bia.y;
                *(float2*)&out[(size_t)m0 * 512 + n0] = v0;
                *(float2*)&out[(size_t)(m0 + 8) * 512 + n0] = v1;
            }
        }
    }
}

// ---------------------------------------------------------------------------
// Kernel 2: flash attention, single-pass fp16 mma.
// 128-row KV staged per pipeline stage; two 64-row sub-tiles computed per
// stage (halves barrier count). 2-stage cp.async.
// smem: KV stage0 [0,36864): K[0,18432) V[18432,36864);
//       KV stage1 [36864,73728); Q [73728,92160). Row stride 144B.
// grid = (H, S/128, B): h fastest -> shm L2 reuse across heads.
// ---------------------------------------------------------------------------
#define RSTR 144
#define KVSTAGE 36864
#define AOF_Q 73728
#define ATT_SMEM 92160

__global__ __launch_bounds__(256, 2) void attn_kernel() {
    extern __shared__ char smc[];
    const uint32_t sb = smem_u32(smc);

    const int h  = blockIdx.x;
    const int qt = blockIdx.y;
    const int b  = blockIdx.z;
    const int tid = threadIdx.x;
    const int lane = tid & 31;
    const int w = tid >> 5;
    const int g = lane >> 2;
    const int tg = lane & 3;
    const int r8 = lane & 7;
    const int mlo = (lane >> 3) & 1;
    const int mhi = lane >> 4;

    const float c1  = 0.125f * 1.4426950408889634f;            // log2e / sqrt(64)
    const float hs2 = exp2f(-(float)h) * 1.4426950408889634f;  // head_scale * log2e

    const size_t hb = (size_t)(h * Bb + b) * Ss;
    const uint32_t* Qw = g_Q16 + (hb + qt * 128) * 32;
    const uint32_t* Kw = g_K16 + hb * 32;
    const uint32_t* Vw = g_V16 + hb * 32;

    // ---- stage Q once (1024 uint4 = 4 cp.async/thread) ----
#pragma unroll
    for (int it = 0; it < 4; it++) {
        int item = tid + it * 256;
        int row = item >> 3, c4 = item & 7;
        cpa16(sb + AOF_Q + (uint32_t)(row * RSTR + c4 * 16),
              Qw + row * 32 + c4 * 4);
    }
    CP_COMMIT();

    // stage 128-row K/V tile kt (2048 uint4 = 8 cp.async/thread) into stage s
    auto stage_kv = [&](int kt, int s) {
#pragma unroll
        for (int it = 0; it < 8; it++) {
            int item = tid + it * 256;
            int side = item >> 10;          // 0 = K, 1 = V
            int idx = item & 1023;
            int row = idx >> 3, c4 = idx & 7;
            const uint32_t* src = (side ? Vw : Kw) + kt * 4096 + row * 32 + c4 * 4;
            cpa16(sb + s * KVSTAGE + side * 18432
                     + (uint32_t)(row * RSTR + c4 * 16), src);
        }
    };

    stage_kv(0, 0);
    CP_COMMIT();

    const uint32_t aQ = sb + AOF_Q + (uint32_t)((w * 16 + mlo * 8 + r8) * RSTR + mhi * 16);
    const uint32_t aKb = sb + (uint32_t)((mhi * 8 + r8) * RSTR + mlo * 16);
    const uint32_t aVb = sb + 18432 + (uint32_t)((mlo * 8 + r8) * RSTR + mhi * 16);

    float oacc[8][4];
#pragma unroll
    for (int nb = 0; nb < 8; nb++)
#pragma unroll
        for (int q = 0; q < 4; q++) oacc[nb][q] = 0.f;
    float ls0 = 0.f, ls1 = 0.f;

    const int q0 = qt * 128 + w * 16 + g;
    const uint32_t* shmp = g_SM16 + ((size_t)b * Ss + q0) * 1024 + tg;

#pragma unroll 1
    for (int kt = 0; kt < 16; kt++) {
        const int s = kt & 1;
        if (kt + 1 < 16) {
            stage_kv(kt + 1, s ^ 1);
            CP_COMMIT();
            CP_WAIT1();
        } else {
            CP_WAIT0();
        }
        __syncthreads();

#pragma unroll
        for (int sub = 0; sub < 2; sub++) {
            const uint32_t aK = aKb + s * KVSTAGE + sub * (64 * RSTR);
            const uint32_t aV = aVb + s * KVSTAGE + sub * (64 * RSTR);

            // ---- S = Q @ K^T (single fp16 pass) ----
            float sacc[8][4];
#pragma unroll
            for (int nb = 0; nb < 8; nb++)
#pragma unroll
                for (int q = 0; q < 4; q++) sacc[nb][q] = 0.f;
#pragma unroll
            for (int kk = 0; kk < 4; kk++) {
                uint32_t qf[4], kf[4];
                ldsm4(qf, aQ + kk * 32);
#pragma unroll
                for (int nbp = 0; nbp < 4; nbp++) {
                    ldsm4(kf, aK + nbp * (16 * RSTR) + kk * 32);
                    mma_f16(sacc[2*nbp],   qf, kf[0], kf[1]);
                    mma_f16(sacc[2*nbp+1], qf, kf[2], kf[3]);
                }
            }

            // ---- softmax -> P fragments (single fp16) ----
            uint32_t pa[4][4];
            const uint32_t* sm_r = shmp + (kt * 2 + sub) * 32;
#pragma unroll
            for (int nb = 0; nb < 8; nb++) {
                float2 s0 = uph2(sm_r[nb * 4]);
                float2 s1 = uph2(sm_r[8 * 1024 + nb * 4]);
                float p00 = exp2f(fmaf(sacc[nb][0], c1, -hs2 * s0.x));
                float p01 = exp2f(fmaf(sacc[nb][1], c1, -hs2 * s0.y));
                float p10 = exp2f(fmaf(sacc[nb][2], c1, -hs2 * s1.x));
                float p11 = exp2f(fmaf(sacc[nb][3], c1, -hs2 * s1.y));
                ls0 += p00 + p01;
                ls1 += p10 + p11;
                uint32_t w0 = pkh2(p00, p01);
                uint32_t w1 = pkh2(p10, p11);
                const int kk2 = nb >> 1;
                if (nb & 1) { pa[kk2][2] = w0; pa[kk2][3] = w1; }
                else        { pa[kk2][0] = w0; pa[kk2][1] = w1; }
            }

            // ---- O += P @ V (single fp16 pass, V via ldmatrix.trans) ----
#pragma unroll
            for (int kk2 = 0; kk2 < 4; kk2++) {
#pragma unroll
                for (int nbp = 0; nbp < 4; nbp++) {
                    uint32_t vf[4];
                    ldsm4t(vf, aV + kk2 * (16 * RSTR) + nbp * 32);
                    mma_f16(oacc[2*nbp],   pa[kk2], vf[0], vf[1]);
                    mma_f16(oacc[2*nbp+1], pa[kk2], vf[2], vf[3]);
                }
            }
        }
        __syncthreads();   // all warps done with stage s before restage
    }

    // ---- epilogue: reduce row sums, scale, write split fp16 O ----
    ls0 += __shfl_xor_sync(0xffffffffu, ls0, 1);
    ls0 += __shfl_xor_sync(0xffffffffu, ls0, 2);
    ls1 += __shfl_xor_sync(0xffffffffu, ls1, 1);
    ls1 += __shfl_xor_sync(0xffffffffu, ls1, 2);
    const float i0 = 1.f / ls0;
    const float i1 = 1.f / ls1;

    const size_t base0 = ((size_t)b * Ss + q0) * 256 + h * 32 + tg;
#pragma unroll
    for (int nb = 0; nb < 8; nb++) {
        uint32_t hi, lo;
        splith2(make_float2(oacc[nb][0] * i0, oacc[nb][1] * i0), hi, lo);
        g_Oh16[base0 + nb * 4] = hi;
        g_Ol16[base0 + nb * 4] = lo;
        splith2(make_float2(oacc[nb][2] * i1, oacc[nb][3] * i1), hi, lo);
        g_Oh16[base0 + 8 * 256 + nb * 4] = hi;
        g_Ol16[base0 + 8 * 256 + nb * 4] = lo;
    }
}

// ---------------------------------------------------------------------------
extern "C" void kernel_launch(void* const* d_in, const int* in_sizes, int n_in,
                              void* d_out, int out_size) {
    const float* x     = (const float*)d_in[0];
    const float* shift = (const float*)d_in[1];
    const float* mask  = (const float*)d_in[2];
    const float* W     = (const float*)d_in[3];
    const float* b     = (const float*)d_in[4];
    const float* Wo    = (const float*)d_in[5];
    const float* bo    = (const float*)d_in[6];
    float* out = (float*)d_out;

    cudaFuncSetAttribute(tc_gemm<0>, cudaFuncAttributeMaxDynamicSharedMemorySize,
                         GEMM_SMEM);
    cudaFuncSetAttribute(tc_gemm<1>, cudaFuncAttributeMaxDynamicSharedMemorySize,
                         GEMM_SMEM);
    cudaFuncSetAttribute(attn_kernel, cudaFuncAttributeMaxDynamicSharedMemorySize,
                         ATT_SMEM);

    // fp16 tables: X hi/lo, W, Wo, fused shift/mask
    presplit<<<2048, 256>>>(x, W, Wo, shift, mask);

    // QKV projection: fp16 2-pass, M64 tiles, pipelined; emits fp16 Q/K/V
    tc_gemm<0><<<dim3(12, 64), 256, GEMM_SMEM>>>(b, nullptr);

    // attention: single-pass fp16, 128-row KV stages, fused shm table
    attn_kernel<<<dim3(Hh, Ss / 128, Bb), 256, ATT_SMEM>>>();

    // output projection: fp16 2-pass, M64 tiles, pipelined
    tc_gemm<1><<<dim3(4, 64), 256, GEMM_SMEM>>>(bo, out);
}